// round 2
// baseline (speedup 1.0000x reference)
#include <cuda_runtime.h>
#include <math.h>

#define Bn   16
#define Hn   512
#define Wn   512
#define HWn  (Hn * Wn)

#define TW   64            // tile width  (outputs)
#define TH   32            // tile height (outputs)
#define EXTW (TW + 6)      // 70 (halo)
#define EXTH (TH + 6)      // 38
#define SRS  72            // s_r row stride (floats), 16B-aligned rows
#define HSS  68            // h-sum row stride (floats), 16B-aligned rows

__device__ double g_sum[Bn], g_sumsq[Bn], g_S[Bn];

__device__ __forceinline__ float warpRed(float v) {
    #pragma unroll
    for (int o = 16; o; o >>= 1) v += __shfl_down_sync(0xffffffffu, v, o);
    return v;
}
__device__ __forceinline__ int refl(int i) {
    i = (i < 0) ? -i : i;
    return (i >= Hn) ? (2 * (Hn - 1) - i) : i;   // Hn == Wn
}

__global__ void k_zero() {
    int i = threadIdx.x;
    if (i < Bn) { g_sum[i] = 0.0; g_sumsq[i] = 0.0; g_S[i] = 0.0; }
}

// Fully fused: residual (channel-summed |gt-out|), gate (vs |gt-ema|),
// per-image sum/sumsq (global variance), separable 7x7 unbiased local
// variance (reflect pad), and per-image gated loss partial sum.
__global__ __launch_bounds__(256) void k_fused(const float* __restrict__ outp,
                                               const float* __restrict__ emap,
                                               const float* __restrict__ gtp) {
    __shared__ float         s_r [EXTH * SRS];   // raw rs tile + halo
    __shared__ float         s_hs[EXTH * HSS];   // horizontal 7-sum
    __shared__ float         s_hq[EXTH * HSS];   // horizontal 7-sum of squares
    __shared__ unsigned char s_g [TH * TW];      // gate bytes (center)
    __shared__ float         sh  [24];

    int b   = blockIdx.z;
    int tx0 = blockIdx.x * TW;
    int ty0 = blockIdx.y * TH;
    int tid = threadIdx.x;

    const float* ob = outp + (size_t)b * 3 * HWn;
    const float* gb = gtp  + (size_t)b * 3 * HWn;
    const float* eb = emap + (size_t)b * 3 * HWn;

    bool edge = (tx0 == 0) || (ty0 == 0) || (tx0 + TW == Wn) || (ty0 + TH == Hn);

    float lsum = 0.f, lsq = 0.f;

    // Phase 1: compute rs over halo tile directly from GMEM; gate + image
    // statistics on center pixels only (each counted exactly once chip-wide).
    for (int i = tid; i < EXTH * EXTW; i += 256) {
        int lr = i / EXTW, lc = i - lr * EXTW;
        int gr, gc;
        if (edge) { gr = refl(ty0 + lr - 3); gc = refl(tx0 + lc - 3); }
        else      { gr = ty0 + lr - 3;       gc = tx0 + lc - 3; }
        int p = gr * Wn + gc;
        float g0 = gb[p], g1 = gb[p + HWn], g2 = gb[p + 2 * HWn];
        float rs = fabsf(g0 - ob[p]) + fabsf(g1 - ob[p + HWn]) + fabsf(g2 - ob[p + 2 * HWn]);
        s_r[lr * SRS + lc] = rs;
        if (lr >= 3 && lr < 3 + TH && lc >= 3 && lc < 3 + TW) {
            float re = fabsf(g0 - eb[p]) + fabsf(g1 - eb[p + HWn]) + fabsf(g2 - eb[p + 2 * HWn]);
            s_g[(lr - 3) * TW + (lc - 3)] = (rs < re) ? 0 : 1;
            lsum += rs; lsq += rs * rs;
        }
    }
    __syncthreads();

    // Phase 2: horizontal 7-taps, 4 outputs/thread via sliding window + float4.
    for (int i = tid; i < EXTH * (TW / 4); i += 256) {
        int row = i >> 4;              // TW/4 == 16
        int g4  = (i & 15) << 2;
        const float* rp = &s_r[row * SRS + g4];
        float4 A = *(const float4*)(rp);
        float4 Bv = *(const float4*)(rp + 4);
        float4 Cv = *(const float4*)(rp + 8);
        float v0=A.x, v1=A.y, v2=A.z, v3=A.w, v4=Bv.x, v5=Bv.y, v6=Bv.z, v7=Bv.w, v8=Cv.x, v9=Cv.y;
        float s0 = v0+v1+v2+v3+v4+v5+v6;
        float s1 = s0 - v0 + v7;
        float s2 = s1 - v1 + v8;
        float s3 = s2 - v2 + v9;
        float q0 = v0*v0+v1*v1+v2*v2+v3*v3+v4*v4+v5*v5+v6*v6;
        float q1 = q0 + (v7*v7 - v0*v0);
        float q2 = q1 + (v8*v8 - v1*v1);
        float q3 = q2 + (v9*v9 - v2*v2);
        *(float4*)&s_hs[row * HSS + g4] = make_float4(s0, s1, s2, s3);
        *(float4*)&s_hq[row * HSS + g4] = make_float4(q0, q1, q2, q3);
    }
    __syncthreads();

    // Phase 3: vertical 7-taps with register sliding window; 8 rows/thread.
    int c  = tid & (TW - 1);
    int r0 = (tid >> 6) * (TH / 4);    // 4 row-groups of 8
    float s = 0.f, q = 0.f;
    #pragma unroll
    for (int d = 0; d < 7; d++) {
        s += s_hs[(r0 + d) * HSS + c];
        q += s_hq[(r0 + d) * HSS + c];
    }
    float acc = 0.f;
    #pragma unroll
    for (int k = 0; k < TH / 4; k++) {
        int r = r0 + k;
        float var = (q - s * s * (1.f / 49.f)) * (1.f / 48.f);
        float rs  = s_r[(r + 3) * SRS + c + 3];
        if (s_g[r * TW + c]) acc += fabsf(var * rs);
        if (k < TH / 4 - 1) {
            s += s_hs[(r + 7) * HSS + c] - s_hs[r * HSS + c];
            q += s_hq[(r + 7) * HSS + c] - s_hq[r * HSS + c];
        }
    }

    // Phase 4: block-reduce (sum, sumsq, loss partial) -> per-image atomics.
    float a0 = warpRed(lsum), a1 = warpRed(lsq), a2 = warpRed(acc);
    int lane = tid & 31, w = tid >> 5;
    if (lane == 0) { sh[w] = a0; sh[8 + w] = a1; sh[16 + w] = a2; }
    __syncthreads();
    if (w == 0) {
        a0 = (lane < 8) ? sh[lane]      : 0.f;
        a1 = (lane < 8) ? sh[8 + lane]  : 0.f;
        a2 = (lane < 8) ? sh[16 + lane] : 0.f;
        a0 = warpRed(a0); a1 = warpRed(a1); a2 = warpRed(a2);
        if (lane == 0) {
            atomicAdd(&g_sum[b],   (double)a0);
            atomicAdd(&g_sumsq[b], (double)a1);
            atomicAdd(&g_S[b],     (double)a2);
        }
    }
}

__global__ void k_final(float* out) {
    double tot = 0.0;
    for (int b = 0; b < Bn; b++) {
        double n   = (double)HWn;
        double var = (g_sumsq[b] - g_sum[b] * g_sum[b] / n) / (n - 1.0);
        tot += pow(var, 0.2) * g_S[b];
    }
    out[0] = (float)(tot / (double)(Bn * 3 * HWn));
}

extern "C" void kernel_launch(void* const* d_in, const int* in_sizes, int n_in,
                              void* d_out, int out_size) {
    const float* outp = (const float*)d_in[0];
    const float* emap = (const float*)d_in[1];
    const float* gtp  = (const float*)d_in[2];
    float* out = (float*)d_out;

    k_zero<<<1, 32>>>();
    dim3 grid(Wn / TW, Hn / TH, Bn);
    k_fused<<<grid, 256>>>(outp, emap, gtp);
    k_final<<<1, 1>>>(out);
}

// round 3
// speedup vs baseline: 1.5401x; 1.5401x over previous
#include <cuda_runtime.h>
#include <math.h>

#define Bn    16
#define Hn    512
#define Wn    512
#define HWn   (Hn * Wn)
#define NPIX  (Bn * HWn)

// localvar tile
#define TW    32
#define TH    32
#define EXTW  38
#define EXTH  38
#define SRS   40   // s_r row stride (floats), rows 16B aligned
#define HSS   36   // h-sum row stride (floats), rows 16B aligned

#define RBLK  4096 // residual blocks (1024 px each; 256 per image)

// Scratch (__device__ globals; every slot fully rewritten each call)
__device__ float g_rsr[NPIX];
__device__ unsigned int g_gatew[NPIX / 4];   // 4 packed gate bytes / word
__device__ float g_psum[RBLK], g_psq[RBLK];  // residual per-block partials
__device__ float g_pS[RBLK];                 // localvar per-block partials

__device__ __forceinline__ float warpRed(float v) {
    #pragma unroll
    for (int o = 16; o; o >>= 1) v += __shfl_down_sync(0xffffffffu, v, o);
    return v;
}
__device__ __forceinline__ double warpRedD(double v) {
    #pragma unroll
    for (int o = 16; o; o >>= 1) v += __shfl_down_sync(0xffffffffu, v, o);
    return v;
}
__device__ __forceinline__ int refl(int i) {
    i = (i < 0) ? -i : i;
    return (i >= Hn) ? (2 * (Hn - 1) - i) : i;
}

// ---------------------------------------------------------------------------
// Residual: rs = sum_c |gt-out|, gate = (rs >= re), per-block sum/sumsq.
// float4 throughout; blocks never straddle images (1024 px/block).
// ---------------------------------------------------------------------------
__global__ __launch_bounds__(256) void k_residual(const float* __restrict__ outp,
                                                  const float* __restrict__ emap,
                                                  const float* __restrict__ gtp) {
    int blk = blockIdx.x;
    int b   = blk >> 8;                      // 256 blocks per image
    int p   = (blk & 255) * 1024 + threadIdx.x * 4;
    size_t base = (size_t)b * 3 * HWn + p;

    float4 g0 = *(const float4*)(gtp  + base);
    float4 g1 = *(const float4*)(gtp  + base + HWn);
    float4 g2 = *(const float4*)(gtp  + base + 2 * HWn);
    float4 o0 = *(const float4*)(outp + base);
    float4 o1 = *(const float4*)(outp + base + HWn);
    float4 o2 = *(const float4*)(outp + base + 2 * HWn);
    float4 e0 = *(const float4*)(emap + base);
    float4 e1 = *(const float4*)(emap + base + HWn);
    float4 e2 = *(const float4*)(emap + base + 2 * HWn);

    float4 rs, re;
    rs.x = fabsf(g0.x-o0.x)+fabsf(g1.x-o1.x)+fabsf(g2.x-o2.x);
    rs.y = fabsf(g0.y-o0.y)+fabsf(g1.y-o1.y)+fabsf(g2.y-o2.y);
    rs.z = fabsf(g0.z-o0.z)+fabsf(g1.z-o1.z)+fabsf(g2.z-o2.z);
    rs.w = fabsf(g0.w-o0.w)+fabsf(g1.w-o1.w)+fabsf(g2.w-o2.w);
    re.x = fabsf(g0.x-e0.x)+fabsf(g1.x-e1.x)+fabsf(g2.x-e2.x);
    re.y = fabsf(g0.y-e0.y)+fabsf(g1.y-e1.y)+fabsf(g2.y-e2.y);
    re.z = fabsf(g0.z-e0.z)+fabsf(g1.z-e1.z)+fabsf(g2.z-e2.z);
    re.w = fabsf(g0.w-e0.w)+fabsf(g1.w-e1.w)+fabsf(g2.w-e2.w);

    int idx4 = b * (HWn / 4) + p / 4;
    *(float4*)(g_rsr + (size_t)b * HWn + p) = rs;
    unsigned int gw = (rs.x < re.x ? 0u : 1u)
                    | (rs.y < re.y ? 0u : 1u) << 8
                    | (rs.z < re.z ? 0u : 1u) << 16
                    | (rs.w < re.w ? 0u : 1u) << 24;
    g_gatew[idx4] = gw;

    float lsum = rs.x + rs.y + rs.z + rs.w;
    float lsq  = rs.x*rs.x + rs.y*rs.y + rs.z*rs.z + rs.w*rs.w;

    lsum = warpRed(lsum); lsq = warpRed(lsq);
    __shared__ float sh_s[8], sh_q[8];
    int lane = threadIdx.x & 31, w = threadIdx.x >> 5;
    if (lane == 0) { sh_s[w] = lsum; sh_q[w] = lsq; }
    __syncthreads();
    if (w == 0) {
        lsum = (lane < 8) ? sh_s[lane] : 0.f;
        lsq  = (lane < 8) ? sh_q[lane] : 0.f;
        lsum = warpRed(lsum); lsq = warpRed(lsq);
        if (lane == 0) { g_psum[blk] = lsum; g_psq[blk] = lsq; }
    }
}

// ---------------------------------------------------------------------------
// 7x7 unbiased local variance (reflect), gated, per-block S partial.
// Separable, sliding-window in both directions.
// ---------------------------------------------------------------------------
__global__ __launch_bounds__(256) void k_localvar() {
    __shared__ float s_r [EXTH * SRS];
    __shared__ float s_hs[EXTH * HSS];
    __shared__ float s_hq[EXTH * HSS];
    __shared__ unsigned int s_gw[TH * (TW / 4)];   // 256 packed gate words

    int b   = blockIdx.z;
    int tx0 = blockIdx.x * TW;
    int ty0 = blockIdx.y * TH;
    int tid = threadIdx.x;

    const float* rb = g_rsr + (size_t)b * HWn;
    bool edge = (tx0 == 0) || (ty0 == 0) || (tx0 + TW == Wn) || (ty0 + TH == Hn);

    // Phase 1: halo tile of rs + packed gates.
    if (edge) {
        for (int i = tid; i < EXTH * EXTW; i += 256) {
            int lr = i / EXTW, lc = i - lr * EXTW;
            s_r[lr * SRS + lc] = rb[refl(ty0 + lr - 3) * Wn + refl(tx0 + lc - 3)];
        }
    } else {
        for (int i = tid; i < EXTH * EXTW; i += 256) {
            int lr = i / EXTW, lc = i - lr * EXTW;
            s_r[lr * SRS + lc] = rb[(ty0 + lr - 3) * Wn + (tx0 + lc - 3)];
        }
    }
    {   // one gate word per thread: row = tid>>3, colword = tid&7
        int r = tid >> 3, cw = tid & 7;
        s_gw[tid] = g_gatew[(b * HWn + (ty0 + r) * Wn + tx0) / 4 + cw];
    }
    __syncthreads();

    // Phase 2: horizontal 7-taps, 4 outputs/thread (sliding + float4).
    for (int i = tid; i < EXTH * (TW / 4); i += 256) {
        int row = i >> 3;
        int g4  = (i & 7) << 2;
        const float* rp = &s_r[row * SRS + g4];
        float4 A = *(const float4*)(rp);
        float4 Bv = *(const float4*)(rp + 4);
        float4 Cv = *(const float4*)(rp + 8);
        float v0=A.x,v1=A.y,v2=A.z,v3=A.w,v4=Bv.x,v5=Bv.y,v6=Bv.z,v7=Bv.w,v8=Cv.x,v9=Cv.y;
        float s0 = v0+v1+v2+v3+v4+v5+v6;
        float s1 = s0 - v0 + v7;
        float s2 = s1 - v1 + v8;
        float s3 = s2 - v2 + v9;
        float q0 = v0*v0+v1*v1+v2*v2+v3*v3+v4*v4+v5*v5+v6*v6;
        float q1 = q0 + (v7*v7 - v0*v0);
        float q2 = q1 + (v8*v8 - v1*v1);
        float q3 = q2 + (v9*v9 - v2*v2);
        *(float4*)&s_hs[row * HSS + g4] = make_float4(s0, s1, s2, s3);
        *(float4*)&s_hq[row * HSS + g4] = make_float4(q0, q1, q2, q3);
    }
    __syncthreads();

    // Phase 3: vertical 7-taps, register sliding window, 4 rows/thread.
    int c  = tid & 31;
    int r0 = (tid >> 5) * 4;
    float s = 0.f, q = 0.f;
    #pragma unroll
    for (int d = 0; d < 7; d++) {
        s += s_hs[(r0 + d) * HSS + c];
        q += s_hq[(r0 + d) * HSS + c];
    }
    float acc = 0.f;
    #pragma unroll
    for (int k = 0; k < 4; k++) {
        int r = r0 + k;
        float var  = (q - s * s * (1.f / 49.f)) * (1.f / 48.f);
        float rs   = s_r[(r + 3) * SRS + c + 3];
        unsigned int gw = s_gw[r * 8 + (c >> 2)];
        if ((gw >> ((c & 3) * 8)) & 1u) acc += fabsf(var * rs);
        if (k < 3) {
            s += s_hs[(r + 7) * HSS + c] - s_hs[r * HSS + c];
            q += s_hq[(r + 7) * HSS + c] - s_hq[r * HSS + c];
        }
    }

    acc = warpRed(acc);
    __shared__ float sh[8];
    int lane = tid & 31, w = tid >> 5;
    if (lane == 0) sh[w] = acc;
    __syncthreads();
    if (w == 0) {
        acc = (lane < 8) ? sh[lane] : 0.f;
        acc = warpRed(acc);
        if (lane == 0)
            g_pS[(blockIdx.z * 16 + blockIdx.y) * 16 + blockIdx.x] = acc;
    }
}

// ---------------------------------------------------------------------------
// Final: per-image var -> pw = var^0.2, loss = sum_b pw_b*S_b / (B*3*H*W).
// One block, 16 warps; warp b reduces image b's 256 partials in double.
// ---------------------------------------------------------------------------
__global__ void k_final(float* out) {
    __shared__ double sh[16];
    int lane = threadIdx.x & 31, b = threadIdx.x >> 5;   // 512 threads, 16 warps
    double s = 0.0, q = 0.0, S = 0.0;
    for (int j = lane; j < 256; j += 32) {
        s += (double)g_psum[b * 256 + j];
        q += (double)g_psq [b * 256 + j];
        S += (double)g_pS  [b * 256 + j];
    }
    s = warpRedD(s); q = warpRedD(q); S = warpRedD(S);
    if (lane == 0) {
        double n   = (double)HWn;
        double var = (q - s * s / n) / (n - 1.0);
        sh[b] = pow(var, 0.2) * S;
    }
    __syncthreads();
    if (threadIdx.x == 0) {
        double tot = 0.0;
        #pragma unroll
        for (int i = 0; i < 16; i++) tot += sh[i];
        out[0] = (float)(tot / (double)((long long)Bn * 3 * HWn));
    }
}

extern "C" void kernel_launch(void* const* d_in, const int* in_sizes, int n_in,
                              void* d_out, int out_size) {
    const float* outp = (const float*)d_in[0];
    const float* emap = (const float*)d_in[1];
    const float* gtp  = (const float*)d_in[2];
    float* out = (float*)d_out;

    k_residual<<<RBLK, 256>>>(outp, emap, gtp);
    dim3 grid(Wn / TW, Hn / TH, Bn);
    k_localvar<<<grid, 256>>>();
    k_final<<<1, 512>>>(out);
}

// round 4
// speedup vs baseline: 1.6320x; 1.0597x over previous
#include <cuda_runtime.h>
#include <math.h>

#define Bn    16
#define Hn    512
#define Wn    512
#define HWn   (Hn * Wn)
#define NPIX  (Bn * HWn)

// localvar tile: 64 wide x 32 tall outputs
#define TW    64
#define TH    32
#define EXTH  38
#define SRS   72   // s_r row stride (cols tx0-4 .. tx0+67)
#define HSS   68   // h-sum row stride (64 outputs + pad)

#define RBLK  4096 // residual blocks (1024 px, 256/image)
#define LBLK  2048 // localvar blocks (8 x 16 x 16)

// Scratch (__device__ globals; rewritten every call)
__device__ float g_rsr[NPIX];                 // signed: sign bit = gate off
__device__ float g_psum[RBLK], g_psq[RBLK];   // residual per-block partials
__device__ float g_pS[LBLK];                  // localvar per-block partials
__device__ unsigned int g_ctr;                // last-block counter (self-resets)

__device__ __forceinline__ float warpRed(float v) {
    #pragma unroll
    for (int o = 16; o; o >>= 1) v += __shfl_down_sync(0xffffffffu, v, o);
    return v;
}
__device__ __forceinline__ double warpRedD(double v) {
    #pragma unroll
    for (int o = 16; o; o >>= 1) v += __shfl_down_sync(0xffffffffu, v, o);
    return v;
}
__device__ __forceinline__ int refl(int i) {
    i = (i < 0) ? -i : i;
    return (i >= Hn) ? (2 * (Hn - 1) - i) : i;
}

// ---------------------------------------------------------------------------
// Residual: rs = sum_c |gt-out|; gate vs sum_c |gt-ema| folded into sign bit;
// per-block sum/sumsq partials for the global variance. float4 throughout.
// ---------------------------------------------------------------------------
__global__ __launch_bounds__(256) void k_residual(const float* __restrict__ outp,
                                                  const float* __restrict__ emap,
                                                  const float* __restrict__ gtp) {
    int blk = blockIdx.x;
    int b   = blk >> 8;
    int p   = (blk & 255) * 1024 + threadIdx.x * 4;
    size_t base = (size_t)b * 3 * HWn + p;

    float4 g0 = *(const float4*)(gtp  + base);
    float4 g1 = *(const float4*)(gtp  + base + HWn);
    float4 g2 = *(const float4*)(gtp  + base + 2 * HWn);
    float4 o0 = *(const float4*)(outp + base);
    float4 o1 = *(const float4*)(outp + base + HWn);
    float4 o2 = *(const float4*)(outp + base + 2 * HWn);
    float4 e0 = *(const float4*)(emap + base);
    float4 e1 = *(const float4*)(emap + base + HWn);
    float4 e2 = *(const float4*)(emap + base + 2 * HWn);

    float4 rs, re;
    rs.x = fabsf(g0.x-o0.x)+fabsf(g1.x-o1.x)+fabsf(g2.x-o2.x);
    rs.y = fabsf(g0.y-o0.y)+fabsf(g1.y-o1.y)+fabsf(g2.y-o2.y);
    rs.z = fabsf(g0.z-o0.z)+fabsf(g1.z-o1.z)+fabsf(g2.z-o2.z);
    rs.w = fabsf(g0.w-o0.w)+fabsf(g1.w-o1.w)+fabsf(g2.w-o2.w);
    re.x = fabsf(g0.x-e0.x)+fabsf(g1.x-e1.x)+fabsf(g2.x-e2.x);
    re.y = fabsf(g0.y-e0.y)+fabsf(g1.y-e1.y)+fabsf(g2.y-e2.y);
    re.z = fabsf(g0.z-e0.z)+fabsf(g1.z-e1.z)+fabsf(g2.z-e2.z);
    re.w = fabsf(g0.w-e0.w)+fabsf(g1.w-e1.w)+fabsf(g2.w-e2.w);

    float4 sv;   // sign bit encodes gate (negative => gated off)
    sv.x = (rs.x < re.x) ? -rs.x : rs.x;
    sv.y = (rs.y < re.y) ? -rs.y : rs.y;
    sv.z = (rs.z < re.z) ? -rs.z : rs.z;
    sv.w = (rs.w < re.w) ? -rs.w : rs.w;
    *(float4*)(g_rsr + (size_t)b * HWn + p) = sv;

    float lsum = rs.x + rs.y + rs.z + rs.w;
    float lsq  = rs.x*rs.x + rs.y*rs.y + rs.z*rs.z + rs.w*rs.w;

    lsum = warpRed(lsum); lsq = warpRed(lsq);
    __shared__ float sh_s[8], sh_q[8];
    int lane = threadIdx.x & 31, w = threadIdx.x >> 5;
    if (lane == 0) { sh_s[w] = lsum; sh_q[w] = lsq; }
    __syncthreads();
    if (w == 0) {
        lsum = (lane < 8) ? sh_s[lane] : 0.f;
        lsq  = (lane < 8) ? sh_q[lane] : 0.f;
        lsum = warpRed(lsum); lsq = warpRed(lsq);
        if (lane == 0) { g_psum[blk] = lsum; g_psq[blk] = lsq; }
    }
}

// ---------------------------------------------------------------------------
// Separable 7x7 unbiased local variance (reflect pad) + gated loss partial,
// with the final per-image combine done by the last-finishing block.
// ---------------------------------------------------------------------------
__global__ __launch_bounds__(256) void k_localvar(float* __restrict__ out) {
    __shared__ float  s_r [EXTH * SRS];   // signed rs, cols tx0-4..tx0+67
    __shared__ float  s_hs[EXTH * HSS];   // horizontal 7-sum of |rs|
    __shared__ float  s_hq[EXTH * HSS];   // horizontal 7-sum of rs^2
    __shared__ float  sh[8];
    __shared__ double shd[16];
    __shared__ bool   isLast;

    int b   = blockIdx.z;
    int tx0 = blockIdx.x * TW;
    int ty0 = blockIdx.y * TH;
    int tid = threadIdx.x;

    const float* rb = g_rsr + (size_t)b * HWn;
    bool edge = (tx0 == 0) || (ty0 == 0) || (tx0 + TW == Wn) || (ty0 + TH == Hn);

    // Phase 1: load signed-rs halo tile (float4 for interior blocks).
    if (!edge) {
        for (int i = tid; i < EXTH * 18; i += 256) {
            int lr = i / 18, lc4 = (i - lr * 18) * 4;
            float4 v = *(const float4*)(rb + (ty0 + lr - 3) * Wn + (tx0 - 4) + lc4);
            *(float4*)&s_r[lr * SRS + lc4] = v;
        }
    } else {
        for (int i = tid; i < EXTH * SRS; i += 256) {
            int lr = i / SRS, lc = i - lr * SRS;
            s_r[lr * SRS + lc] = rb[refl(ty0 + lr - 3) * Wn + refl(tx0 - 4 + lc)];
        }
    }
    __syncthreads();

    // Phase 2: horizontal 7-taps, 4 outputs/thread, aligned float4 LDS.
    // Outputs c=g4..g4+3 need smem cols g4+1..g4+10; read j=g4..g4+11.
    for (int i = tid; i < EXTH * (TW / 4); i += 256) {
        int row = i >> 4;
        int g4  = (i & 15) << 2;
        const float* rp = &s_r[row * SRS + g4];
        float4 A = *(const float4*)(rp);
        float4 Bv = *(const float4*)(rp + 4);
        float4 Cv = *(const float4*)(rp + 8);
        float v0 = fabsf(A.y), v1 = fabsf(A.z), v2 = fabsf(A.w);
        float v3 = fabsf(Bv.x), v4 = fabsf(Bv.y), v5 = fabsf(Bv.z), v6 = fabsf(Bv.w);
        float v7 = fabsf(Cv.x), v8 = fabsf(Cv.y), v9 = fabsf(Cv.z);
        float s0 = v0+v1+v2+v3+v4+v5+v6;
        float s1 = s0 - v0 + v7;
        float s2 = s1 - v1 + v8;
        float s3 = s2 - v2 + v9;
        float q0 = v0*v0+v1*v1+v2*v2+v3*v3+v4*v4+v5*v5+v6*v6;
        float q1 = q0 + (v7*v7 - v0*v0);
        float q2 = q1 + (v8*v8 - v1*v1);
        float q3 = q2 + (v9*v9 - v2*v2);
        *(float4*)&s_hs[row * HSS + g4] = make_float4(s0, s1, s2, s3);
        *(float4*)&s_hq[row * HSS + g4] = make_float4(q0, q1, q2, q3);
    }
    __syncthreads();

    // Phase 3: vertical 7-taps, register sliding window, 8 rows/thread.
    int c  = tid & (TW - 1);
    int r0 = (tid >> 6) * 8;
    float s = 0.f, q = 0.f;
    #pragma unroll
    for (int d = 0; d < 7; d++) {
        s += s_hs[(r0 + d) * HSS + c];
        q += s_hq[(r0 + d) * HSS + c];
    }
    float acc = 0.f;
    #pragma unroll
    for (int k = 0; k < 8; k++) {
        int r = r0 + k;
        float var = (q - s * s * (1.f / 49.f)) * (1.f / 48.f);
        float raw = s_r[(r + 3) * SRS + c + 4];
        if (!(__float_as_uint(raw) >> 31))     // gate = sign bit clear
            acc += fabsf(var) * raw;           // raw >= 0 here
        if (k < 7) {
            s += s_hs[(r + 7) * HSS + c] - s_hs[r * HSS + c];
            q += s_hq[(r + 7) * HSS + c] - s_hq[r * HSS + c];
        }
    }

    acc = warpRed(acc);
    int lane = tid & 31, w = tid >> 5;
    if (lane == 0) sh[w] = acc;
    __syncthreads();
    if (w == 0) {
        acc = (lane < 8) ? sh[lane] : 0.f;
        acc = warpRed(acc);
        if (lane == 0)
            g_pS[(blockIdx.z * 16 + blockIdx.y) * 8 + blockIdx.x] = acc;
    }

    // Last-finishing block performs the final combine (no extra launch).
    __threadfence();
    if (tid == 0) {
        unsigned int t = atomicAdd(&g_ctr, 1u);
        isLast = (t == LBLK - 1);
    }
    __syncthreads();
    if (!isLast) return;

    // warp w reduces images 2w and 2w+1 (double accumulation).
    #pragma unroll
    for (int u = 0; u < 2; u++) {
        int img = (w << 1) | u;
        double ds = 0.0, dq = 0.0, dS = 0.0;
        #pragma unroll
        for (int j = lane; j < 256; j += 32) {
            ds += (double)g_psum[img * 256 + j];
            dq += (double)g_psq [img * 256 + j];
        }
        #pragma unroll
        for (int j = lane; j < 128; j += 32)
            dS += (double)g_pS[img * 128 + j];
        ds = warpRedD(ds); dq = warpRedD(dq); dS = warpRedD(dS);
        if (lane == 0) {
            double n   = (double)HWn;
            double var = (dq - ds * ds / n) / (n - 1.0);
            shd[img] = pow(var, 0.2) * dS;
        }
    }
    __syncthreads();
    if (tid == 0) {
        double tot = 0.0;
        #pragma unroll
        for (int i = 0; i < 16; i++) tot += shd[i];
        out[0] = (float)(tot / (double)((long long)Bn * 3 * HWn));
        g_ctr = 0;   // reset for next graph replay
    }
}

extern "C" void kernel_launch(void* const* d_in, const int* in_sizes, int n_in,
                              void* d_out, int out_size) {
    const float* outp = (const float*)d_in[0];
    const float* emap = (const float*)d_in[1];
    const float* gtp  = (const float*)d_in[2];
    float* out = (float*)d_out;

    k_residual<<<RBLK, 256>>>(outp, emap, gtp);
    dim3 grid(Wn / TW, Hn / TH, Bn);
    k_localvar<<<grid, 256>>>(out);
}